// round 1
// baseline (speedup 1.0000x reference)
#include <cuda_runtime.h>
#include <cstdint>

// PackedViterbi: out[b] = logsumexp_i V_L[i], V_t[i] = logsumexp_j(theta[t,b,i,j] + V_{t-1}[j])
// Strategy: one CTA per sequence b (64 CTAs). 512 threads: row i = tid>>3 (64 rows),
// octet oc = tid&7 handles 8 consecutive j. Base-2 log domain:
//   w_j  : normalized log2-scale state (double-buffered in SMEM)
//   A    : running scalar offset (double, thread 0) with true W_j = w_j + A
// Per step: s_i = sum_j 2^(theta*log2e + w_j); w'_i = log2(s_i) - 6 - w_old[0];
//           A += 6 + w_old[0]. Stale-pivot feedback keeps w bounded (|w| < ~10),
// no max pass needed, ONE __syncthreads per step.
// Depth-2 register prefetch of theta tiles hides DRAM latency (loads are V-independent).

static constexpr int S = 64;

__device__ __forceinline__ float ex2_(float x) {
    float y; asm("ex2.approx.ftz.f32 %0, %1;" : "=f"(y) : "f"(x)); return y;
}
__device__ __forceinline__ float lg2_(float x) {
    float y; asm("lg2.approx.f32 %0, %1;" : "=f"(y) : "f"(x)); return y;
}

__global__ __launch_bounds__(512, 1)
void packed_viterbi_kernel(const float* __restrict__ theta,
                           const int*   __restrict__ lengths,
                           float*       __restrict__ out,
                           int B)
{
    const int b   = blockIdx.x;
    const int tid = threadIdx.x;
    const int i   = tid >> 3;   // row (target state)  0..63
    const int oc  = tid & 7;    // octet within row    0..7
    const int L   = lengths[b];

    __shared__ float wbuf[2][S];

    if (tid < S) wbuf[0][tid] = 0.0f;
    __syncthreads();

    const float  L2E = 1.4426950408889634f;
    const size_t stepStride = (size_t)B * S * S;
    const float* p = theta + (size_t)b * S * S + (size_t)i * S + (size_t)oc * 8;

    // depth-2 prefetch buffers: 8 floats each
    float4 a0, a1, b0, b1;
    {
        const float4* q0 = reinterpret_cast<const float4*>(p);
        a0 = q0[0]; a1 = q0[1];
        const int t1 = (L > 1) ? 1 : 0;
        const float4* q1 = reinterpret_cast<const float4*>(p + (size_t)t1 * stepStride);
        b0 = q1[0]; b1 = q1[1];
    }

    double A = 0.0;   // meaningful in thread 0 only
    int t = 0;

#define VITERBI_STEP(PB0, PB1)                                                        \
    {                                                                                 \
        float4 c0 = PB0, c1 = PB1;                                                    \
        int tp = t + 2; tp = (tp < L) ? tp : t; /* safe in-range dummy */             \
        const float4* qp =                                                            \
            reinterpret_cast<const float4*>(p + (size_t)tp * stepStride);             \
        PB0 = qp[0]; PB1 = qp[1];                                                     \
        const float* w  = wbuf[t & 1];                                                \
        const float  pivot = w[0];                                                    \
        const float* wj = w + oc * 8;                                                 \
        float acc;                                                                    \
        acc  = ex2_(fmaf(c0.x, L2E, wj[0]));                                          \
        acc += ex2_(fmaf(c0.y, L2E, wj[1]));                                          \
        acc += ex2_(fmaf(c0.z, L2E, wj[2]));                                          \
        acc += ex2_(fmaf(c0.w, L2E, wj[3]));                                          \
        acc += ex2_(fmaf(c1.x, L2E, wj[4]));                                          \
        acc += ex2_(fmaf(c1.y, L2E, wj[5]));                                          \
        acc += ex2_(fmaf(c1.z, L2E, wj[6]));                                          \
        acc += ex2_(fmaf(c1.w, L2E, wj[7]));                                          \
        acc += __shfl_xor_sync(0xffffffffu, acc, 1);                                  \
        acc += __shfl_xor_sync(0xffffffffu, acc, 2);                                  \
        acc += __shfl_xor_sync(0xffffffffu, acc, 4);                                  \
        if (oc == 0)  wbuf[(t & 1) ^ 1][i] = lg2_(acc) - 6.0f - pivot;                \
        if (tid == 0) A += (double)(6.0f + pivot);                                    \
        __syncthreads();                                                              \
    }

    while (t < L) {
        VITERBI_STEP(a0, a1);        // even t
        if (++t >= L) break;
        VITERBI_STEP(b0, b1);        // odd t
        ++t;
    }
#undef VITERBI_STEP

    if (tid == 0) {
        const float* w = wbuf[L & 1];   // last written buffer (buffer 0 if L==0)
        float m = w[0];
        #pragma unroll
        for (int k = 1; k < S; ++k) m = fmaxf(m, w[k]);
        float s = 0.0f;
        #pragma unroll
        for (int k = 0; k < S; ++k) s += ex2_(w[k] - m);
        const double vt = ((double)lg2_(s) + (double)m + A) * 0.6931471805599453094;
        out[b] = (float)vt;
    }
}

extern "C" void kernel_launch(void* const* d_in, const int* in_sizes, int n_in,
                              void* d_out, int out_size)
{
    const float* theta   = (const float*)d_in[0];
    const int*   lengths = (const int*)d_in[1];
    float*       out     = (float*)d_out;
    const int B = in_sizes[1];          // 64
    packed_viterbi_kernel<<<B, 512>>>(theta, lengths, out, B);
}

// round 2
// speedup vs baseline: 1.0698x; 1.0698x over previous
#include <cuda_runtime.h>
#include <cstdint>

// PackedViterbi in the LINEAR domain:
//   u_t = E_t @ u_{t-1},  E = 2^(theta * log2(e)),  with per-step scalar rescale
//   u' = s * c,  c = rcp(s0 of previous step)  (stale pivot, no extra barrier),
//   A += lg2(s0_prev) tracked in double by tid 0.  Vt = ln2 * (lg2(sum u_L) + A).
//
// Why: the 4096 ex2/step are state-independent, so they are computed ONE STEP
// AHEAD on prefetched theta (depth-3 LDG pipeline), overlapping the critical
// dot->shuffle->barrier chain instead of serializing behind it.
//
// One CTA per sequence (64 CTAs), 512 threads: row i = tid>>3, octet oc = tid&7.

static constexpr int S = 64;

__device__ __forceinline__ float ex2_(float x) {
    float y; asm("ex2.approx.ftz.f32 %0, %1;" : "=f"(y) : "f"(x)); return y;
}
__device__ __forceinline__ float lg2_(float x) {
    float y; asm("lg2.approx.f32 %0, %1;" : "=f"(y) : "f"(x)); return y;
}
__device__ __forceinline__ float rcp_(float x) {
    float y; asm("rcp.approx.ftz.f32 %0, %1;" : "=f"(y) : "f"(x)); return y;
}

__global__ __launch_bounds__(512, 1)
void packed_viterbi_kernel(const float* __restrict__ theta,
                           const int*   __restrict__ lengths,
                           float*       __restrict__ out,
                           int B)
{
    const int b   = blockIdx.x;
    const int tid = threadIdx.x;
    const int i   = tid >> 3;
    const int oc  = tid & 7;
    const int L   = lengths[b];

    __shared__ __align__(16) float ubuf[2][S];
    __shared__ float cbuf[2];

    if (tid < S) ubuf[0][tid] = 1.0f;
    if (tid == 0) cbuf[0] = 1.0f;
    __syncthreads();

    const float  L2E = 1.4426950408889634f;
    const size_t stepStride = (size_t)B * S * S;
    const float* p = theta + (size_t)b * S * S + (size_t)i * S + (size_t)oc * 8;

    // depth-3 raw-theta pipeline + double-buffered converted E
    float4 r0a, r0b, r1a, r1b, r2a, r2b;
    {
        const float4* q;
        q = reinterpret_cast<const float4*>(p);
        r0a = q[0]; r0b = q[1];
        const int t1 = (1 < L) ? 1 : (L - 1);
        q = reinterpret_cast<const float4*>(p + (size_t)t1 * stepStride);
        r1a = q[0]; r1b = q[1];
        const int t2 = (2 < L) ? 2 : (L - 1);
        q = reinterpret_cast<const float4*>(p + (size_t)t2 * stepStride);
        r2a = q[0]; r2b = q[1];
    }

    float4 e0a, e0b, e1a, e1b, e2a, e2b;
    e0a.x = ex2_(r0a.x * L2E); e0a.y = ex2_(r0a.y * L2E);
    e0a.z = ex2_(r0a.z * L2E); e0a.w = ex2_(r0a.w * L2E);
    e0b.x = ex2_(r0b.x * L2E); e0b.y = ex2_(r0b.y * L2E);
    e0b.z = ex2_(r0b.z * L2E); e0b.w = ex2_(r0b.w * L2E);

    double A = 0.0;        // meaningful in tid 0 only
    float  s0prev = 1.0f;  // meaningful in tid 0 only
    int t = 0;

#define VSTEP(EA, EB, RNA, RNB, ENA, ENB, RLA, RLB)                                   \
    {                                                                                 \
        const float* ub  = ubuf[t & 1];                                               \
        const float  csc = cbuf[t & 1];                                               \
        const float4 uu0 = *reinterpret_cast<const float4*>(ub + oc * 8);             \
        const float4 uu1 = *reinterpret_cast<const float4*>(ub + oc * 8 + 4);         \
        int tp = t + 3; tp = (tp < L) ? tp : (L - 1);                                 \
        const float4* qp =                                                            \
            reinterpret_cast<const float4*>(p + (size_t)tp * stepStride);             \
        RLA = qp[0]; RLB = qp[1];                                                     \
        /* convert E for step t+1 (off critical path, fills MUFU queue) */           \
        ENA.x = ex2_(RNA.x * L2E); ENA.y = ex2_(RNA.y * L2E);                         \
        ENA.z = ex2_(RNA.z * L2E); ENA.w = ex2_(RNA.w * L2E);                         \
        ENB.x = ex2_(RNB.x * L2E); ENB.y = ex2_(RNB.y * L2E);                         \
        ENB.z = ex2_(RNB.z * L2E); ENB.w = ex2_(RNB.w * L2E);                         \
        /* dot: 8 products, two accumulator chains */                                 \
        float a0 = EA.x * uu0.x;                                                      \
        float a1 = EA.y * uu0.y;                                                      \
        a0 = fmaf(EA.z, uu0.z, a0); a1 = fmaf(EA.w, uu0.w, a1);                       \
        a0 = fmaf(EB.x, uu1.x, a0); a1 = fmaf(EB.y, uu1.y, a1);                       \
        a0 = fmaf(EB.z, uu1.z, a0); a1 = fmaf(EB.w, uu1.w, a1);                       \
        float acc = a0 + a1;                                                          \
        acc += __shfl_xor_sync(0xffffffffu, acc, 1);                                  \
        acc += __shfl_xor_sync(0xffffffffu, acc, 2);                                  \
        acc += __shfl_xor_sync(0xffffffffu, acc, 4);                                  \
        if (oc == 0) ubuf[(t & 1) ^ 1][i] = acc * csc;                                \
        if (tid == 0) {                                                               \
            A += (double)lg2_(s0prev);                                                \
            cbuf[(t & 1) ^ 1] = rcp_(acc);                                            \
            s0prev = acc;                                                             \
        }                                                                             \
        __syncthreads();                                                              \
    }

    for (;;) {
        VSTEP(e0a, e0b, r1a, r1b, e1a, e1b, r0a, r0b);
        if (++t >= L) break;
        VSTEP(e1a, e1b, r2a, r2b, e2a, e2b, r1a, r1b);
        if (++t >= L) break;
        VSTEP(e2a, e2b, r0a, r0b, e0a, e0b, r2a, r2b);
        if (++t >= L) break;
    }
#undef VSTEP

    if (tid == 0) {
        const float* w = ubuf[L & 1];
        float s = 0.0f;
        #pragma unroll
        for (int k = 0; k < S; ++k) s += w[k];
        const double vt = ((double)lg2_(s) + A) * 0.6931471805599453094;
        out[b] = (float)vt;
    }
}

extern "C" void kernel_launch(void* const* d_in, const int* in_sizes, int n_in,
                              void* d_out, int out_size)
{
    const float* theta   = (const float*)d_in[0];
    const int*   lengths = (const int*)d_in[1];
    float*       out     = (float*)d_out;
    const int B = in_sizes[1];   // 64
    packed_viterbi_kernel<<<B, 512>>>(theta, lengths, out, B);
}